// round 17
// baseline (speedup 1.0000x reference)
#include <cuda_runtime.h>
#include <cstddef>

#define B_      128
#define NNZ_    128
#define H_      128
#define KOUT_   4096
#define FDIM_   135909

// Intermediate val1 [B, H] — device global scratch (no allocations allowed).
__device__ float g_val1[B_ * H_];

// ---------------------------------------------------------------------------
// Layer 1 (measured optimum — at HBM 64B-atom spec for random 4B gathers):
// val1[b,h] = relu( sum_i v[b,i] * W1[h, fidx[b,i]] + b1[h] )
// One block per b, 128 threads = one per h; indices/values staged in smem;
// i-loop unrolled x16 so ~16 independent gathers are in flight per thread.
// ---------------------------------------------------------------------------
__global__ __launch_bounds__(128) void layer1_kernel(
    const float* __restrict__ inv,
    const int*   __restrict__ fidx,
    const float* __restrict__ W1,
    const float* __restrict__ b1)
{
    const int b = blockIdx.x;
    const int h = threadIdx.x;

    __shared__ int   sidx[NNZ_];
    __shared__ float sval[NNZ_];
    sidx[h] = fidx[(b << 7) + h];
    sval[h] = inv[(b << 7) + h];
    __syncthreads();

    const float* w = W1 + (size_t)h * FDIM_;
    float acc = b1[h];

    #pragma unroll
    for (int i0 = 0; i0 < NNZ_; i0 += 16) {
        float wv[16];
        #pragma unroll
        for (int j = 0; j < 16; j++) wv[j] = __ldg(w + sidx[i0 + j]);
        #pragma unroll
        for (int j = 0; j < 16; j++) acc = fmaf(sval[i0 + j], wv[j], acc);
    }

    g_val1[(b << 7) + h] = fmaxf(acc, 0.0f);
}

// ---------------------------------------------------------------------------
// Layer 2 (R12 shape — measured optimum, ~38.8-40.4us / ~71-74% DRAM):
//   val2[b,k] = <val1[b,:], W2[lab[b,k],:]> + b2[lab[b,k]]
// Warp = 4 outputs via 4 coalesced 512B W2-row loads in flight; no smem, no
// barriers; labels via ONE uniform evict-first int4 load; bias gather
// overlapped with the plain 4x butterfly reduce (do NOT restructure the
// load batch or the reduce — every variant tried perturbed ptxas's load
// scheduling and regressed); evict-first output stores.
// Micro-tweaks vs R12 (both off the critical path):
//  - lanes 4-7 write out_lab in parallel with lanes 0-3 writing out
//  - the int->float label conversion is hoisted before the reduce
// ---------------------------------------------------------------------------
__global__ __launch_bounds__(256) void layer2_kernel(
    const int*   __restrict__ lab,
    const float* __restrict__ W2,
    const float* __restrict__ b2,
    float*       __restrict__ out,
    float*       __restrict__ out_lab)   // may be null
{
    const int warp  = threadIdx.x >> 5;
    const int lane  = threadIdx.x & 31;
    const int b     = blockIdx.x >> 7;                      // 128 blocks per b
    const int kbase = ((blockIdx.x & 127) << 5) + (warp << 2);
    const int base  = (b << 12) + kbase;

    // one uniform 16B label load (broadcast wavefront), evict-first
    const int4 r4 = __ldcs(reinterpret_cast<const int4*>(lab + base));
    const int rows[4] = { r4.x, r4.y, r4.z, r4.w };

    // val1[b] lane-slice straight from L1/L2 (hot: 128 blocks reuse each row)
    const float4 sv = __ldg(reinterpret_cast<const float4*>(g_val1 + (b << 7)) + lane);

    float acc[4];
    #pragma unroll
    for (int j = 0; j < 4; j++) {
        const float4 wv = __ldg(reinterpret_cast<const float4*>(W2) +
                                ((size_t)rows[j] << 5) + lane);
        acc[j] = wv.x * sv.x + wv.y * sv.y + wv.z * sv.z + wv.w * sv.w;
    }

    // issue the bias gather before the reduces so it flies during the shfls;
    // hoist the int->float label conversion off the store path too
    const int  lj    = lane & 3;
    float      bias  = (lane < 4) ? __ldg(b2 + rows[lj]) : 0.0f;
    const float flab = (float)rows[lj];

    #pragma unroll
    for (int j = 0; j < 4; j++) {
        #pragma unroll
        for (int o = 16; o > 0; o >>= 1)
            acc[j] += __shfl_xor_sync(0xffffffffu, acc[j], o);
    }

    // lanes 0-3 store val2, lanes 4-7 store the label echo (parallel wavefronts)
    if (lane < 4) {
        __stcs(out + base + lj, acc[lj] + bias);
    } else if (lane < 8 && out_lab) {
        __stcs(out_lab + base + lj, flab);
    }
}

// ---------------------------------------------------------------------------
extern "C" void kernel_launch(void* const* d_in, const int* in_sizes, int n_in,
                              void* d_out, int out_size)
{
    const float* inv  = (const float*)d_in[0];   // in_values        [B, NNZ]
    const int*   fidx = (const int*)  d_in[1];   // active_in_indices[B, NNZ]
    const int*   lab  = (const int*)  d_in[2];   // active_label_idx [B, KOUT]
    const float* W1   = (const float*)d_in[3];   // [H, FDIM]
    const float* b1   = (const float*)d_in[4];   // [H]
    const float* W2   = (const float*)d_in[5];   // [C, H]
    const float* b2   = (const float*)d_in[6];   // [C]

    float* out = (float*)d_out;
    const int n_val2 = B_ * KOUT_;
    float* out_lab = (out_size >= 2 * n_val2) ? (out + n_val2) : nullptr;

    layer1_kernel<<<B_, 128>>>(inv, fidx, W1, b1);
    layer2_kernel<<<(B_ * KOUT_) / 32, 256>>>(lab, W2, b2, out, out_lab);
}